// round 9
// baseline (speedup 1.0000x reference)
#include <cuda_runtime.h>
#include <cuda_bf16.h>
#include <cstdint>

#define B_ROWS 2048
#define CDIM   65536
#define DK     256
#define NNEG   50
#define CAP    6144
#define NTILES 512                 // 128-wide max tiles (2 halves per N-tile)

// ---------------- device global scratch (no allocation calls) --------------
__device__ float g_scores[(size_t)B_ROWS * CDIM];          // 512 MB
__device__ float g_tilemax[(size_t)B_ROWS * NTILES];       // 4 MB (lab-excluded)
__device__ float g_rowloss[B_ROWS];
__device__ int   g_lab[B_ROWS];
__device__ __nv_bfloat16 g_ahi[(size_t)B_ROWS * DK];
__device__ __nv_bfloat16 g_alo[(size_t)B_ROWS * DK];
__device__ __nv_bfloat16 g_bhi[(size_t)CDIM * DK];         // 32 MB
__device__ __nv_bfloat16 g_blo[(size_t)CDIM * DK];         // 32 MB

// ---------------- PTX helpers (baseline ISA only) --------------------------
__device__ __forceinline__ uint32_t smem_u32(const void* p) {
    uint32_t a;
    asm("{ .reg .u64 t; cvta.to.shared.u64 t, %1; cvt.u32.u64 %0, t; }"
        : "=r"(a) : "l"(p));
    return a;
}
__device__ __forceinline__ void cpa16(uint32_t dst, const void* src) {
    asm volatile("cp.async.cg.shared.global [%0], [%1], 16;"
                 :: "r"(dst), "l"(__cvta_generic_to_global(src)));
}
#define CPA_COMMIT() asm volatile("cp.async.commit_group;" ::: "memory")
#define CPA_WAIT0()  asm volatile("cp.async.wait_group 0;" ::: "memory")
#define CPA_WAIT1()  asm volatile("cp.async.wait_group 1;" ::: "memory")

#define LDSM4(r, addr)                                                         \
    asm volatile("ldmatrix.sync.aligned.m8n8.x4.shared.b16 {%0,%1,%2,%3},[%4];"\
        : "=r"((r)[0]), "=r"((r)[1]), "=r"((r)[2]), "=r"((r)[3]) : "r"(addr))

#define MMA16816(d, a, b0, b1)                                                 \
    asm volatile("mma.sync.aligned.m16n8k16.row.col.f32.bf16.bf16.f32 "        \
        "{%0,%1,%2,%3},{%4,%5,%6,%7},{%8,%9},{%0,%1,%2,%3};"                   \
        : "+f"((d)[0]), "+f"((d)[1]), "+f"((d)[2]), "+f"((d)[3])               \
        : "r"((a)[0]), "r"((a)[1]), "r"((a)[2]), "r"((a)[3]),                  \
          "r"(b0), "r"(b1))

__device__ __forceinline__ uint32_t pkbf(__nv_bfloat16 a, __nv_bfloat16 b) {
    __nv_bfloat162 p; p.x = a; p.y = b;
    return *(uint32_t*)&p;
}

// ---------------- misc helpers ---------------------------------------------
__device__ __forceinline__ unsigned monof(float v) {
    unsigned b = __float_as_uint(v);
    return (b & 0x80000000u) ? ~b : (b | 0x80000000u);
}
__device__ __forceinline__ float unmonof(unsigned u) {
    unsigned b = (u & 0x80000000u) ? (u & 0x7fffffffu) : ~u;
    return __uint_as_float(b);
}
__device__ __forceinline__ int blockSumI(int v, int* sred, int tid) {
#pragma unroll
    for (int o = 16; o; o >>= 1) v += __shfl_xor_sync(0xffffffffu, v, o);
    if ((tid & 31) == 0) sred[tid >> 5] = v;
    __syncthreads();
    int tot = 0;
#pragma unroll
    for (int w = 0; w < 8; w++) tot += sred[w];
    __syncthreads();
    return tot;
}
__device__ __forceinline__ float blockSumF(float v, float* sred, int tid) {
#pragma unroll
    for (int o = 16; o; o >>= 1) v += __shfl_xor_sync(0xffffffffu, v, o);
    if ((tid & 31) == 0) sred[tid >> 5] = v;
    __syncthreads();
    float tot = 0.f;
#pragma unroll
    for (int w = 0; w < 8; w++) tot += sred[w];
    __syncthreads();
    return tot;
}
__device__ __forceinline__ float blockMinF(float v, float* sred, int tid) {
#pragma unroll
    for (int o = 16; o; o >>= 1) v = fminf(v, __shfl_xor_sync(0xffffffffu, v, o));
    if ((tid & 31) == 0) sred[tid >> 5] = v;
    __syncthreads();
    float tot = sred[0];
#pragma unroll
    for (int w = 1; w < 8; w++) tot = fminf(tot, sred[w]);
    __syncthreads();
    return tot;
}

// ===========================================================================
// Kernel 0: decode labels (int64 vs int32 ambiguity) + clamp
// ===========================================================================
__global__ void k_declab(const void* __restrict__ labp) {
    __shared__ int s_nz;
    const unsigned* w = (const unsigned*)labp;
    if (threadIdx.x == 0) s_nz = 0;
    __syncthreads();
    int nz = 0;
    for (int i = threadIdx.x; i < B_ROWS / 2; i += 256)
        if (w[2 * i + 1] != 0u) nz = 1;
    if (nz) atomicOr(&s_nz, 1);
    __syncthreads();
    bool is64 = (s_nz == 0);
    for (int r = threadIdx.x; r < B_ROWS; r += 256) {
        long long v = is64 ? ((const long long*)labp)[r] : (long long)((const int*)labp)[r];
        if (v < 0) v = 0;
        if (v > CDIM - 1) v = CDIM - 1;
        g_lab[r] = (int)v;
    }
}

// ===========================================================================
// Kernel 0b: fp32 -> (hi, lo) bf16 split
// ===========================================================================
__global__ __launch_bounds__(256) void k_conv(const float* __restrict__ S,
                                              __nv_bfloat16* __restrict__ H,
                                              __nv_bfloat16* __restrict__ L) {
    size_t i = (size_t)blockIdx.x * 256 + threadIdx.x;  // one float4 each
    float4 v = ((const float4*)S)[i];
    __nv_bfloat16 h0 = __float2bfloat16(v.x), h1 = __float2bfloat16(v.y);
    __nv_bfloat16 h2 = __float2bfloat16(v.z), h3 = __float2bfloat16(v.w);
    __nv_bfloat16 l0 = __float2bfloat16(v.x - __bfloat162float(h0));
    __nv_bfloat16 l1 = __float2bfloat16(v.y - __bfloat162float(h1));
    __nv_bfloat16 l2 = __float2bfloat16(v.z - __bfloat162float(h2));
    __nv_bfloat16 l3 = __float2bfloat16(v.w - __bfloat162float(h3));
    ((uint2*)H)[i] = make_uint2(pkbf(h0, h1), pkbf(h2, h3));
    ((uint2*)L)[i] = make_uint2(pkbf(l0, l1), pkbf(l2, l3));
}

// ===========================================================================
// Kernel 1: HMMA GEMM. CTA tile 128(M)x256(N), 8 warps in 2x4 (warp 64x64).
// 3-term bf16 split in fp32: Ah*Bh + Ah*Bl + Al*Bh.
// Stage = k-chunk of 32; rows padded to 80B.
// Stage offsets: Ahi 0, Alo 10240, Bhi 20480, Blo 40960 (61440/stage, x2).
// Epilogue: streaming score store + lab-excluded per-row max per 128-halftile.
// ===========================================================================
__global__ __launch_bounds__(256, 1) void k_gemm_mma() {
    extern __shared__ __align__(16) char smem[];
    const uint32_t sb = smem_u32(smem);
    const int tid = threadIdx.x, lane = tid & 31, wid = tid >> 5;
    const int wm = wid & 1, wn = wid >> 1;          // warp grid 2(M) x 4(N)
    const int g = lane >> 2, tig = lane & 3;
    const int m0 = blockIdx.x * 128;
    const int n0t = blockIdx.y;                      // 256-wide N tile index

    float acc[4][8][4] = {};                         // [mi][ni][4]

    const int lrow = tid >> 2, lpc = tid & 3;        // loader: row(64/iter), piece

    const uint32_t aRow = (uint32_t)((wm * 64 + (lane & 15)) * 80 +
                                     ((lane >> 4) & 1) * 16);
    const uint32_t bRow = (uint32_t)((wn * 64 + (lane & 7) + ((lane >> 4) & 1) * 8) * 80 +
                                     ((lane >> 3) & 1) * 16);

#define LOAD_STAGE(kt, bufi)                                                   \
    do {                                                                       \
        uint32_t st_ = sb + (bufi) * 61440;                                    \
        int kof_ = (kt) * 32 + lpc * 8;                                        \
        _Pragma("unroll")                                                      \
        for (int h_ = 0; h_ < 2; h_++) {  /* A: 128 rows */                    \
            int r_ = lrow + h_ * 64;                                           \
            size_t ga_ = (size_t)(m0 + r_) * DK + kof_;                        \
            uint32_t so_ = st_ + r_ * 80 + lpc * 16;                           \
            cpa16(so_, g_ahi + ga_);                                           \
            cpa16(so_ + 10240, g_alo + ga_);                                   \
        }                                                                      \
        _Pragma("unroll")                                                      \
        for (int h_ = 0; h_ < 4; h_++) {  /* B: 256 rows */                    \
            int r_ = lrow + h_ * 64;                                           \
            size_t gb_ = (size_t)(n0t * 256 + r_) * DK + kof_;                 \
            uint32_t so_ = st_ + 20480 + r_ * 80 + lpc * 16;                   \
            cpa16(so_, g_bhi + gb_);                                           \
            cpa16(so_ + 20480, g_blo + gb_);                                   \
        }                                                                      \
        CPA_COMMIT();                                                          \
    } while (0)

    LOAD_STAGE(0, 0);
    int buf = 0;
#pragma unroll 1
    for (int kt = 0; kt < 8; kt++) {
        if (kt < 7) { LOAD_STAGE(kt + 1, buf ^ 1); CPA_WAIT1(); }
        else        { CPA_WAIT0(); }
        __syncthreads();

        const uint32_t st = sb + buf * 61440;
#pragma unroll
        for (int kk = 0; kk < 2; kk++) {
            const uint32_t kb = kk * 32;  // 16 bf16 = 32 bytes
            uint32_t ah[4][4], bh[8][2], bl[8][2];
#pragma unroll
            for (int mi = 0; mi < 4; mi++)
                LDSM4(ah[mi], st + aRow + mi * (16 * 80) + kb);
#pragma unroll
            for (int p = 0; p < 4; p++) {
                uint32_t r4[4];
                LDSM4(r4, st + 20480 + bRow + p * (16 * 80) + kb);
                bh[2 * p][0] = r4[0]; bh[2 * p][1] = r4[1];
                bh[2 * p + 1][0] = r4[2]; bh[2 * p + 1][1] = r4[3];
                LDSM4(r4, st + 40960 + bRow + p * (16 * 80) + kb);
                bl[2 * p][0] = r4[0]; bl[2 * p][1] = r4[1];
                bl[2 * p + 1][0] = r4[2]; bl[2 * p + 1][1] = r4[3];
            }
#pragma unroll
            for (int mi = 0; mi < 4; mi++)
#pragma unroll
                for (int ni = 0; ni < 8; ni++)
                    MMA16816(acc[mi][ni], ah[mi], bh[ni][0], bh[ni][1]);
#pragma unroll
            for (int mi = 0; mi < 4; mi++)
#pragma unroll
                for (int ni = 0; ni < 8; ni++)
                    MMA16816(acc[mi][ni], ah[mi], bl[ni][0], bl[ni][1]);
            uint32_t al[4][4];
#pragma unroll
            for (int mi = 0; mi < 4; mi++)
                LDSM4(al[mi], st + 10240 + aRow + mi * (16 * 80) + kb);
#pragma unroll
            for (int mi = 0; mi < 4; mi++)
#pragma unroll
                for (int ni = 0; ni < 8; ni++)
                    MMA16816(acc[mi][ni], al[mi], bh[ni][0], bh[ni][1]);
        }
        __syncthreads();
        buf ^= 1;
    }
#undef LOAD_STAGE

    // ---- epilogue: store scores + per-row lab-excluded max per warp ----
    float* sf = (float*)smem;  // [4 wn][128 rows]
#pragma unroll
    for (int mi = 0; mi < 4; mi++) {
        int row0 = m0 + wm * 64 + mi * 16 + g;
        int row1 = row0 + 8;
        int lab0 = g_lab[row0], lab1 = g_lab[row1];
        float mx0 = -3.402823466e38f, mx1 = -3.402823466e38f;
#pragma unroll
        for (int ni = 0; ni < 8; ni++) {
            int col = n0t * 256 + wn * 64 + ni * 8 + tig * 2;
            float c0 = acc[mi][ni][0], c1 = acc[mi][ni][1];
            float c2 = acc[mi][ni][2], c3 = acc[mi][ni][3];
            __stcs((float2*)(g_scores + (size_t)row0 * CDIM + col),
                   make_float2(c0, c1));
            __stcs((float2*)(g_scores + (size_t)row1 * CDIM + col),
                   make_float2(c2, c3));
            if (col != lab0)     mx0 = fmaxf(mx0, c0);
            if (col + 1 != lab0) mx0 = fmaxf(mx0, c1);
            if (col != lab1)     mx1 = fmaxf(mx1, c2);
            if (col + 1 != lab1) mx1 = fmaxf(mx1, c3);
        }
#pragma unroll
        for (int o = 1; o <= 2; o <<= 1) {
            mx0 = fmaxf(mx0, __shfl_xor_sync(0xffffffffu, mx0, o));
            mx1 = fmaxf(mx1, __shfl_xor_sync(0xffffffffu, mx1, o));
        }
        if (tig == 0) {
            sf[wn * 128 + wm * 64 + mi * 16 + g]     = mx0;
            sf[wn * 128 + wm * 64 + mi * 16 + g + 8] = mx1;
        }
    }
    __syncthreads();
    // warp n-halves: wn{0,1} -> 128-half 0, wn{2,3} -> half 1
    if (tid < 128) {
        int row = m0 + tid;
        float h0 = fmaxf(sf[tid], sf[128 + tid]);
        float h1 = fmaxf(sf[256 + tid], sf[384 + tid]);
        g_tilemax[(size_t)row * NTILES + n0t * 2]     = h0;
        g_tilemax[(size_t)row * NTILES + n0t * 2 + 1] = h1;
    }
}

// ===========================================================================
// Kernel 2: per row -> exact top-50 negatives. Pass A: 512 lab-excluded
// 128-col tile maxima (2KB/row) -> theta. Pass B: scan ONLY tiles with
// tilemax >= theta (exact filter; ~50 tiles/row), compact candidates,
// binary search on monotone keys. One 256-thread block per row.
// ===========================================================================
__global__ __launch_bounds__(256) void k_topk() {
    const int row = blockIdx.x;
    const int tid = threadIdx.x;
    const float* rp = g_scores + (size_t)row * CDIM;
    const int lab = g_lab[row];

    __shared__ float    s_max[256];
    __shared__ unsigned s_list[CAP];
    __shared__ unsigned short s_tiles[NTILES];
    __shared__ unsigned s_cnt, s_nt;
    __shared__ int      s_ired[8];
    __shared__ float    s_fred[8];

    // ---- pass A: thread max over 2 tile-maxima ----
    const float2* tm2 = (const float2*)(g_tilemax + (size_t)row * NTILES);
    float2 tv = tm2[tid];
    float lmax = fmaxf(tv.x, tv.y);
    s_max[tid] = lmax;
    __syncthreads();

    float gmax = -3.402823466e38f;
    int c = 0;
#pragma unroll 8
    for (int j = 0; j < 256; j++) {
        float m = s_max[j];
        gmax = fmaxf(gmax, m);
        c += (m > lmax);
    }
    float cand = (c < NNEG) ? lmax : 3.402823466e38f;
    float theta = blockMinF(cand, s_fred, tid);   // <= v50, count(>=theta) >= 50

    float posv = rp[lab];
    float M = fmaxf(gmax, posv);
    if (tid == 0) { s_cnt = 0; s_nt = 0; }
    __syncthreads();

    // ---- pass B: list hot tiles, then warp-per-tile candidate compaction ----
    if (tv.x >= theta) { unsigned p = atomicAdd(&s_nt, 1u); s_tiles[p] = (unsigned short)(2 * tid); }
    if (tv.y >= theta) { unsigned p = atomicAdd(&s_nt, 1u); s_tiles[p] = (unsigned short)(2 * tid + 1); }
    __syncthreads();
    const int nt = (int)s_nt;
    const int lane = tid & 31, w = tid >> 5;
    for (int cb = 0; cb < nt; cb += 8) {
        int li = cb + w;
        if (li < nt) {
            int t = s_tiles[li];
            int base = t * 128 + lane * 4;
            float4 v = *(const float4*)(rp + base);
            if (v.x >= theta && base + 0 != lab) { unsigned p = atomicAdd(&s_cnt, 1u); if (p < CAP) s_list[p] = monof(v.x); }
            if (v.y >= theta && base + 1 != lab) { unsigned p = atomicAdd(&s_cnt, 1u); if (p < CAP) s_list[p] = monof(v.y); }
            if (v.z >= theta && base + 2 != lab) { unsigned p = atomicAdd(&s_cnt, 1u); if (p < CAP) s_list[p] = monof(v.z); }
            if (v.w >= theta && base + 3 != lab) { unsigned p = atomicAdd(&s_cnt, 1u); if (p < CAP) s_list[p] = monof(v.w); }
        }
    }
    __syncthreads();
    unsigned cnt = s_cnt;

    float Sneg, Sexp;

    if (cnt <= CAP) {
        unsigned long long lo = (unsigned long long)monof(theta);
        unsigned long long hi = 0xffffffffull;
        while (lo < hi) {
            unsigned long long mid = lo + (hi - lo + 1) / 2;
            int lc = 0;
            for (unsigned i = tid; i < cnt; i += 256)
                lc += ((unsigned long long)s_list[i] >= mid);
            int tot = blockSumI(lc, s_ired, tid);
            if (tot >= NNEG) lo = mid; else hi = mid - 1;
        }
        unsigned long long ucut = lo + 1;
        int lk1 = 0; float lS = 0.f, lE = 0.f;
        for (unsigned i = tid; i < cnt; i += 256) {
            unsigned long long u = s_list[i];
            if (u >= ucut) {
                float x = unmonof((unsigned)u);
                lk1++; lS += x; lE += expf(x - M);
            }
        }
        int k1 = blockSumI(lk1, s_ired, tid);
        float S1 = blockSumF(lS, s_fred, tid);
        float E1 = blockSumF(lE, s_fred, tid);
        float vstar = unmonof((unsigned)lo);
        float n2 = (float)(NNEG - k1);
        Sneg = S1 + n2 * vstar;
        Sexp = E1 + n2 * expf(vstar - M);
    } else {
        // exact fallback (massive ties): binary search with full-row scans
        const float4* rp4 = (const float4*)rp;
        unsigned long long lo = (unsigned long long)monof(theta);
        unsigned long long hi = 0xffffffffull;
        while (lo < hi) {
            unsigned long long mid = lo + (hi - lo + 1) / 2;
            int lc = 0;
            for (int i = tid; i < CDIM / 4; i += 256) {
                float4 v = rp4[i];
                int base = i * 4;
                if (base + 0 != lab) lc += ((unsigned long long)monof(v.x) >= mid);
                if (base + 1 != lab) lc += ((unsigned long long)monof(v.y) >= mid);
                if (base + 2 != lab) lc += ((unsigned long long)monof(v.z) >= mid);
                if (base + 3 != lab) lc += ((unsigned long long)monof(v.w) >= mid);
            }
            int tot = blockSumI(lc, s_ired, tid);
            if (tot >= NNEG) lo = mid; else hi = mid - 1;
        }
        unsigned long long ucut = lo + 1;
        int lk1 = 0; float lS = 0.f, lE = 0.f;
        for (int i = tid; i < CDIM / 4; i += 256) {
            float4 v = rp4[i];
            int base = i * 4;
            if (base + 0 != lab && (unsigned long long)monof(v.x) >= ucut) { lk1++; lS += v.x; lE += expf(v.x - M); }
            if (base + 1 != lab && (unsigned long long)monof(v.y) >= ucut) { lk1++; lS += v.y; lE += expf(v.y - M); }
            if (base + 2 != lab && (unsigned long long)monof(v.z) >= ucut) { lk1++; lS += v.z; lE += expf(v.z - M); }
            if (base + 3 != lab && (unsigned long long)monof(v.w) >= ucut) { lk1++; lS += v.w; lE += expf(v.w - M); }
        }
        int k1 = blockSumI(lk1, s_ired, tid);
        float S1 = blockSumF(lS, s_fred, tid);
        float E1 = blockSumF(lE, s_fred, tid);
        float vstar = unmonof((unsigned)lo);
        float n2 = (float)(NNEG - k1);
        Sneg = S1 + n2 * vstar;
        Sexp = E1 + n2 * expf(vstar - M);
    }

    if (tid == 0) {
        float lse = M + logf(Sexp + expf(posv - M));
        // targets: t0 = 0.9 + 0.1/500 = 0.9002, tj = 0.0002 (x50), sum = 0.9102
        g_rowloss[row] = 0.9102f * lse - 0.9002f * posv - 0.0002f * Sneg;
    }
}

// ===========================================================================
// Kernel 3: mean over rows -> scalar
// ===========================================================================
__global__ void k_final(float* __restrict__ out) {
    __shared__ float s[256];
    int tid = threadIdx.x;
    float a = 0.f;
    for (int i = tid; i < B_ROWS; i += 256) a += g_rowloss[i];
    s[tid] = a;
    __syncthreads();
    for (int st = 128; st > 0; st >>= 1) {
        if (tid < st) s[tid] += s[tid + st];
        __syncthreads();
    }
    if (tid == 0) out[0] = s[0] * (1.0f / (float)B_ROWS);
}

// ===========================================================================
extern "C" void kernel_launch(void* const* d_in, const int* in_sizes, int n_in,
                              void* d_out, int out_size) {
    const float* f = nullptr;
    const float* cen = nullptr;
    const void* lab = nullptr;
    for (int i = 0; i < n_in; i++) {
        long long sz = in_sizes[i];
        if (sz == (long long)B_ROWS * DK) f = (const float*)d_in[i];
        else if (sz == (long long)CDIM * DK) cen = (const float*)d_in[i];
        else if (sz == (long long)B_ROWS) lab = d_in[i];
    }
    if (!f) f = (const float*)d_in[0];
    if (!cen) cen = (const float*)d_in[1];
    if (!lab) lab = d_in[2];

    const int SMEM_SZ = 2 * 61440;  // two stages of (Ahi|Alo|Bhi|Blo)
    static int s_attr_done = 0;
    if (!s_attr_done) {
        cudaFuncSetAttribute(k_gemm_mma,
                             cudaFuncAttributeMaxDynamicSharedMemorySize, SMEM_SZ);
        s_attr_done = 1;
    }

    __nv_bfloat16 *ahi, *alo, *bhi, *blo;
    cudaGetSymbolAddress((void**)&ahi, g_ahi);
    cudaGetSymbolAddress((void**)&alo, g_alo);
    cudaGetSymbolAddress((void**)&bhi, g_bhi);
    cudaGetSymbolAddress((void**)&blo, g_blo);

    k_declab<<<1, 256>>>(lab);
    k_conv<<<(B_ROWS * DK) / (256 * 4), 256>>>(f, ahi, alo);
    k_conv<<<(CDIM * DK) / (256 * 4), 256>>>(cen, bhi, blo);
    dim3 grid(16, 256);  // x = M tiles (co-resident CTAs share a B tile), y = N
    k_gemm_mma<<<grid, 256, SMEM_SZ>>>();
    k_topk<<<B_ROWS, 256>>>();
    k_final<<<1, 256>>>((float*)d_out);
}

// round 10
// speedup vs baseline: 1.8623x; 1.8623x over previous
#include <cuda_runtime.h>
#include <cuda_bf16.h>
#include <cstdint>

#define B_ROWS 2048
#define CDIM   65536
#define DK     256
#define NNEG   50
#define CAP    6144
#define NTILES 512                 // 128-wide N tiles

// ---------------- device global scratch (no allocation calls) --------------
__device__ float g_scores[(size_t)B_ROWS * CDIM];          // 512 MB
__device__ float g_tilemax[(size_t)B_ROWS * NTILES];       // 4 MB (lab-excluded)
__device__ float g_rowloss[B_ROWS];
__device__ int   g_lab[B_ROWS];
__device__ __nv_bfloat16 g_ahi[(size_t)B_ROWS * DK];
__device__ __nv_bfloat16 g_alo[(size_t)B_ROWS * DK];
__device__ __nv_bfloat16 g_bhi[(size_t)CDIM * DK];         // 32 MB
__device__ __nv_bfloat16 g_blo[(size_t)CDIM * DK];         // 32 MB

// ---------------- PTX helpers (baseline ISA only) --------------------------
__device__ __forceinline__ uint32_t smem_u32(const void* p) {
    uint32_t a;
    asm("{ .reg .u64 t; cvta.to.shared.u64 t, %1; cvt.u32.u64 %0, t; }"
        : "=r"(a) : "l"(p));
    return a;
}
__device__ __forceinline__ void cpa16(uint32_t dst, const void* src) {
    asm volatile("cp.async.cg.shared.global [%0], [%1], 16;"
                 :: "r"(dst), "l"(__cvta_generic_to_global(src)));
}
#define CPA_COMMIT() asm volatile("cp.async.commit_group;" ::: "memory")
#define CPA_WAIT0()  asm volatile("cp.async.wait_group 0;" ::: "memory")
#define CPA_WAIT1()  asm volatile("cp.async.wait_group 1;" ::: "memory")

#define LDSM4(r, addr)                                                         \
    asm volatile("ldmatrix.sync.aligned.m8n8.x4.shared.b16 {%0,%1,%2,%3},[%4];"\
        : "=r"((r)[0]), "=r"((r)[1]), "=r"((r)[2]), "=r"((r)[3]) : "r"(addr))

#define MMA16816(d, a, b0, b1)                                                 \
    asm volatile("mma.sync.aligned.m16n8k16.row.col.f32.bf16.bf16.f32 "        \
        "{%0,%1,%2,%3},{%4,%5,%6,%7},{%8,%9},{%0,%1,%2,%3};"                   \
        : "+f"((d)[0]), "+f"((d)[1]), "+f"((d)[2]), "+f"((d)[3])               \
        : "r"((a)[0]), "r"((a)[1]), "r"((a)[2]), "r"((a)[3]),                  \
          "r"(b0), "r"(b1))

__device__ __forceinline__ uint32_t pkbf(__nv_bfloat16 a, __nv_bfloat16 b) {
    __nv_bfloat162 p; p.x = a; p.y = b;
    return *(uint32_t*)&p;
}

// ---------------- misc helpers ---------------------------------------------
__device__ __forceinline__ unsigned monof(float v) {
    unsigned b = __float_as_uint(v);
    return (b & 0x80000000u) ? ~b : (b | 0x80000000u);
}
__device__ __forceinline__ float unmonof(unsigned u) {
    unsigned b = (u & 0x80000000u) ? (u & 0x7fffffffu) : ~u;
    return __uint_as_float(b);
}
__device__ __forceinline__ int blockSumI(int v, int* sred, int tid) {
#pragma unroll
    for (int o = 16; o; o >>= 1) v += __shfl_xor_sync(0xffffffffu, v, o);
    if ((tid & 31) == 0) sred[tid >> 5] = v;
    __syncthreads();
    int tot = 0;
#pragma unroll
    for (int w = 0; w < 8; w++) tot += sred[w];
    __syncthreads();
    return tot;
}
__device__ __forceinline__ float blockSumF(float v, float* sred, int tid) {
#pragma unroll
    for (int o = 16; o; o >>= 1) v += __shfl_xor_sync(0xffffffffu, v, o);
    if ((tid & 31) == 0) sred[tid >> 5] = v;
    __syncthreads();
    float tot = 0.f;
#pragma unroll
    for (int w = 0; w < 8; w++) tot += sred[w];
    __syncthreads();
    return tot;
}
__device__ __forceinline__ float blockMinF(float v, float* sred, int tid) {
#pragma unroll
    for (int o = 16; o; o >>= 1) v = fminf(v, __shfl_xor_sync(0xffffffffu, v, o));
    if ((tid & 31) == 0) sred[tid >> 5] = v;
    __syncthreads();
    float tot = sred[0];
#pragma unroll
    for (int w = 1; w < 8; w++) tot = fminf(tot, sred[w]);
    __syncthreads();
    return tot;
}

// ===========================================================================
// Kernel 0: decode labels (int64 vs int32 ambiguity) + clamp
// ===========================================================================
__global__ void k_declab(const void* __restrict__ labp) {
    __shared__ int s_nz;
    const unsigned* w = (const unsigned*)labp;
    if (threadIdx.x == 0) s_nz = 0;
    __syncthreads();
    int nz = 0;
    for (int i = threadIdx.x; i < B_ROWS / 2; i += 256)
        if (w[2 * i + 1] != 0u) nz = 1;
    if (nz) atomicOr(&s_nz, 1);
    __syncthreads();
    bool is64 = (s_nz == 0);
    for (int r = threadIdx.x; r < B_ROWS; r += 256) {
        long long v = is64 ? ((const long long*)labp)[r] : (long long)((const int*)labp)[r];
        if (v < 0) v = 0;
        if (v > CDIM - 1) v = CDIM - 1;
        g_lab[r] = (int)v;
    }
}

// ===========================================================================
// Kernel 0b: fp32 -> (hi, lo) bf16 split
// ===========================================================================
__global__ __launch_bounds__(256) void k_conv(const float* __restrict__ S,
                                              __nv_bfloat16* __restrict__ H,
                                              __nv_bfloat16* __restrict__ L) {
    size_t i = (size_t)blockIdx.x * 256 + threadIdx.x;  // one float4 each
    float4 v = ((const float4*)S)[i];
    __nv_bfloat16 h0 = __float2bfloat16(v.x), h1 = __float2bfloat16(v.y);
    __nv_bfloat16 h2 = __float2bfloat16(v.z), h3 = __float2bfloat16(v.w);
    __nv_bfloat16 l0 = __float2bfloat16(v.x - __bfloat162float(h0));
    __nv_bfloat16 l1 = __float2bfloat16(v.y - __bfloat162float(h1));
    __nv_bfloat16 l2 = __float2bfloat16(v.z - __bfloat162float(h2));
    __nv_bfloat16 l3 = __float2bfloat16(v.w - __bfloat162float(h3));
    ((uint2*)H)[i] = make_uint2(pkbf(h0, h1), pkbf(h2, h3));
    ((uint2*)L)[i] = make_uint2(pkbf(l0, l1), pkbf(l2, l3));
}

// ===========================================================================
// Kernel 1: HMMA GEMM. CTA tile 128(M)x128(N), 8 warps 2x4 (warp 64x32).
// 3-term bf16 split in fp32: Ah*Bh + Ah*Bl + Al*Bh.
// 3-stage cp.async pipeline, ONE __syncthreads per stage.
// Stage = k-chunk of 32, XOR-swizzled 64B rows (piece ^= (row>>1)&3):
//   Ahi 0, Alo 8192, Bhi 16384, Blo 24576  (32768/stage, x3 = 96KB, 2 CTA/SM)
// Epilogue: streaming score store + lab-excluded per-row tile max.
// ===========================================================================
__global__ __launch_bounds__(256, 2) void k_gemm_mma() {
    extern __shared__ __align__(16) char smem[];
    const uint32_t sb = smem_u32(smem);
    const int tid = threadIdx.x, lane = tid & 31, wid = tid >> 5;
    const int wm = wid & 1, wn = wid >> 1;          // warp grid 2(M) x 4(N)
    const int g = lane >> 2, tig = lane & 3;
    const int m0 = blockIdx.x * 128;
    const int n0t = blockIdx.y;                      // 128-wide N tile index

    float acc[4][4][4] = {};                         // [mi][ni][4]

    // loader lane mapping: row 0..63 (+64), 16B piece 0..3
    const int lrow = tid >> 2, lpc = tid & 3;
    const uint32_t swzL = (uint32_t)((lpc ^ ((lrow >> 1) & 3)) * 16);

    // ldmatrix lane constants (xor term is lane-constant within each frag)
    const int r15 = lane & 15, khalf = (lane >> 4) & 1;
    const uint32_t aBase = (uint32_t)((wm * 64 + r15) * 64);
    const uint32_t aS0 = (uint32_t)(((khalf) ^ ((r15 >> 1) & 3)) * 16);
    const int rb = (lane & 7) + ((lane >> 4) & 1) * 8, kbh = (lane >> 3) & 1;
    const uint32_t bBase = (uint32_t)((wn * 32 + rb) * 64);
    const uint32_t bS0 = (uint32_t)(((kbh) ^ ((rb >> 1) & 3)) * 16);

#define LOAD_STAGE(kt, bufi)                                                   \
    do {                                                                       \
        uint32_t st_ = sb + (bufi) * 32768;                                    \
        int kof_ = (kt) * 32 + lpc * 8;                                        \
        _Pragma("unroll")                                                      \
        for (int h_ = 0; h_ < 2; h_++) {                                       \
            int r_ = lrow + h_ * 64;                                           \
            size_t ga_ = (size_t)(m0 + r_) * DK + kof_;                        \
            size_t gb_ = (size_t)(n0t * 128 + r_) * DK + kof_;                 \
            uint32_t so_ = st_ + r_ * 64 + swzL;                               \
            cpa16(so_ +     0, g_ahi + ga_);                                   \
            cpa16(so_ +  8192, g_alo + ga_);                                   \
            cpa16(so_ + 16384, g_bhi + gb_);                                   \
            cpa16(so_ + 24576, g_blo + gb_);                                   \
        }                                                                      \
        CPA_COMMIT();                                                          \
    } while (0)

    LOAD_STAGE(0, 0);
    LOAD_STAGE(1, 1);

#pragma unroll 1
    for (int kt = 0; kt < 8; kt++) {
        if (kt < 7) CPA_WAIT1(); else CPA_WAIT0();
        __syncthreads();
        if (kt + 2 < 8) LOAD_STAGE(kt + 2, (kt + 2) % 3);

        const uint32_t st = sb + (kt % 3) * 32768;
#pragma unroll
        for (int kk = 0; kk < 2; kk++) {
            const uint32_t aS = kk ? (aS0 ^ 32) : aS0;
            const uint32_t bS = kk ? (bS0 ^ 32) : bS0;
            uint32_t ah[4][4], bh[4][2], bl[4][2];
#pragma unroll
            for (int mi = 0; mi < 4; mi++)
                LDSM4(ah[mi], st + aBase + mi * 1024 + aS);
#pragma unroll
            for (int p = 0; p < 2; p++) {
                uint32_t r4[4];
                LDSM4(r4, st + 16384 + bBase + p * 1024 + bS);
                bh[2 * p][0] = r4[0]; bh[2 * p][1] = r4[1];
                bh[2 * p + 1][0] = r4[2]; bh[2 * p + 1][1] = r4[3];
                LDSM4(r4, st + 24576 + bBase + p * 1024 + bS);
                bl[2 * p][0] = r4[0]; bl[2 * p][1] = r4[1];
                bl[2 * p + 1][0] = r4[2]; bl[2 * p + 1][1] = r4[3];
            }
#pragma unroll
            for (int mi = 0; mi < 4; mi++)
#pragma unroll
                for (int ni = 0; ni < 4; ni++)
                    MMA16816(acc[mi][ni], ah[mi], bh[ni][0], bh[ni][1]);
#pragma unroll
            for (int mi = 0; mi < 4; mi++)
#pragma unroll
                for (int ni = 0; ni < 4; ni++)
                    MMA16816(acc[mi][ni], ah[mi], bl[ni][0], bl[ni][1]);
            uint32_t al[4][4];
#pragma unroll
            for (int mi = 0; mi < 4; mi++)
                LDSM4(al[mi], st + 8192 + aBase + mi * 1024 + aS);
#pragma unroll
            for (int mi = 0; mi < 4; mi++)
#pragma unroll
                for (int ni = 0; ni < 4; ni++)
                    MMA16816(acc[mi][ni], al[mi], bh[ni][0], bh[ni][1]);
        }
    }
#undef LOAD_STAGE
    __syncthreads();   // smem reuse for the reduction below

    // ---- epilogue: store scores + lab-excluded row max for this tile ----
    float* sf = (float*)smem;  // [4 wn][128 rows]
#pragma unroll
    for (int mi = 0; mi < 4; mi++) {
        int row0 = m0 + wm * 64 + mi * 16 + g;
        int row1 = row0 + 8;
        int lab0 = g_lab[row0], lab1 = g_lab[row1];
        float mx0 = -3.402823466e38f, mx1 = -3.402823466e38f;
#pragma unroll
        for (int ni = 0; ni < 4; ni++) {
            int col = n0t * 128 + wn * 32 + ni * 8 + tig * 2;
            float c0 = acc[mi][ni][0], c1 = acc[mi][ni][1];
            float c2 = acc[mi][ni][2], c3 = acc[mi][ni][3];
            __stcs((float2*)(g_scores + (size_t)row0 * CDIM + col),
                   make_float2(c0, c1));
            __stcs((float2*)(g_scores + (size_t)row1 * CDIM + col),
                   make_float2(c2, c3));
            if (col != lab0)     mx0 = fmaxf(mx0, c0);
            if (col + 1 != lab0) mx0 = fmaxf(mx0, c1);
            if (col != lab1)     mx1 = fmaxf(mx1, c2);
            if (col + 1 != lab1) mx1 = fmaxf(mx1, c3);
        }
#pragma unroll
        for (int o = 1; o <= 2; o <<= 1) {
            mx0 = fmaxf(mx0, __shfl_xor_sync(0xffffffffu, mx0, o));
            mx1 = fmaxf(mx1, __shfl_xor_sync(0xffffffffu, mx1, o));
        }
        if (tig == 0) {
            sf[wn * 128 + wm * 64 + mi * 16 + g]     = mx0;
            sf[wn * 128 + wm * 64 + mi * 16 + g + 8] = mx1;
        }
    }
    __syncthreads();
    if (tid < 128) {
        float m = fmaxf(fmaxf(sf[tid], sf[128 + tid]),
                        fmaxf(sf[256 + tid], sf[384 + tid]));
        g_tilemax[(size_t)(m0 + tid) * NTILES + n0t] = m;
    }
}

// ===========================================================================
// Kernel 2: per row -> exact top-50 negatives. Pass A: 512 lab-excluded
// tile maxima (2KB/row) -> theta. Pass B: scan ONLY tiles with
// tilemax >= theta (exact filter; ~50 tiles/row), compact candidates,
// binary search on monotone keys. One 256-thread block per row.
// ===========================================================================
__global__ __launch_bounds__(256) void k_topk() {
    const int row = blockIdx.x;
    const int tid = threadIdx.x;
    const float* rp = g_scores + (size_t)row * CDIM;
    const int lab = g_lab[row];

    __shared__ float    s_max[256];
    __shared__ unsigned s_list[CAP];
    __shared__ unsigned short s_tiles[NTILES];
    __shared__ unsigned s_cnt, s_nt;
    __shared__ int      s_ired[8];
    __shared__ float    s_fred[8];

    // ---- pass A: thread max over 2 tile-maxima ----
    const float2* tm2 = (const float2*)(g_tilemax + (size_t)row * NTILES);
    float2 tv = tm2[tid];
    float lmax = fmaxf(tv.x, tv.y);
    s_max[tid] = lmax;
    __syncthreads();

    float gmax = -3.402823466e38f;
    int c = 0;
#pragma unroll 8
    for (int j = 0; j < 256; j++) {
        float m = s_max[j];
        gmax = fmaxf(gmax, m);
        c += (m > lmax);
    }
    float cand = (c < NNEG) ? lmax : 3.402823466e38f;
    float theta = blockMinF(cand, s_fred, tid);   // <= v50, count(>=theta) >= 50

    float posv = rp[lab];
    float M = fmaxf(gmax, posv);
    if (tid == 0) { s_cnt = 0; s_nt = 0; }
    __syncthreads();

    // ---- pass B: list hot tiles, then warp-per-tile candidate compaction ----
    if (tv.x >= theta) { unsigned p = atomicAdd(&s_nt, 1u); s_tiles[p] = (unsigned short)(2 * tid); }
    if (tv.y >= theta) { unsigned p = atomicAdd(&s_nt, 1u); s_tiles[p] = (unsigned short)(2 * tid + 1); }
    __syncthreads();
    const int nt = (int)s_nt;
    const int lane = tid & 31, w = tid >> 5;
    for (int cb = 0; cb < nt; cb += 8) {
        int li = cb + w;
        if (li < nt) {
            int t = s_tiles[li];
            int base = t * 128 + lane * 4;
            float4 v = *(const float4*)(rp + base);
            if (v.x >= theta && base + 0 != lab) { unsigned p = atomicAdd(&s_cnt, 1u); if (p < CAP) s_list[p] = monof(v.x); }
            if (v.y >= theta && base + 1 != lab) { unsigned p = atomicAdd(&s_cnt, 1u); if (p < CAP) s_list[p] = monof(v.y); }
            if (v.z >= theta && base + 2 != lab) { unsigned p = atomicAdd(&s_cnt, 1u); if (p < CAP) s_list[p] = monof(v.z); }
            if (v.w >= theta && base + 3 != lab) { unsigned p = atomicAdd(&s_cnt, 1u); if (p < CAP) s_list[p] = monof(v.w); }
        }
    }
    __syncthreads();
    unsigned cnt = s_cnt;

    float Sneg, Sexp;

    if (cnt <= CAP) {
        unsigned long long lo = (unsigned long long)monof(theta);
        unsigned long long hi = 0xffffffffull;
        while (lo < hi) {
            unsigned long long mid = lo + (hi - lo + 1) / 2;
            int lc = 0;
            for (unsigned i = tid; i < cnt; i += 256)
                lc += ((unsigned long long)s_list[i] >= mid);
            int tot = blockSumI(lc, s_ired, tid);
            if (tot >= NNEG) lo = mid; else hi = mid - 1;
        }
        unsigned long long ucut = lo + 1;
        int lk1 = 0; float lS = 0.f, lE = 0.f;
        for (unsigned i = tid; i < cnt; i += 256) {
            unsigned long long u = s_list[i];
            if (u >= ucut) {
                float x = unmonof((unsigned)u);
                lk1++; lS += x; lE += expf(x - M);
            }
        }
        int k1 = blockSumI(lk1, s_ired, tid);
        float S1 = blockSumF(lS, s_fred, tid);
        float E1 = blockSumF(lE, s_fred, tid);
        float vstar = unmonof((unsigned)lo);
        float n2 = (float)(NNEG - k1);
        Sneg = S1 + n2 * vstar;
        Sexp = E1 + n2 * expf(vstar - M);
    } else {
        // exact fallback (massive ties): binary search with full-row scans
        const float4* rp4 = (const float4*)rp;
        unsigned long long lo = (unsigned long long)monof(theta);
        unsigned long long hi = 0xffffffffull;
        while (lo < hi) {
            unsigned long long mid = lo + (hi - lo + 1) / 2;
            int lc = 0;
            for (int i = tid; i < CDIM / 4; i += 256) {
                float4 v = rp4[i];
                int base = i * 4;
                if (base + 0 != lab) lc += ((unsigned long long)monof(v.x) >= mid);
                if (base + 1 != lab) lc += ((unsigned long long)monof(v.y) >= mid);
                if (base + 2 != lab) lc += ((unsigned long long)monof(v.z) >= mid);
                if (base + 3 != lab) lc += ((unsigned long long)monof(v.w) >= mid);
            }
            int tot = blockSumI(lc, s_ired, tid);
            if (tot >= NNEG) lo = mid; else hi = mid - 1;
        }
        unsigned long long ucut = lo + 1;
        int lk1 = 0; float lS = 0.f, lE = 0.f;
        for (int i = tid; i < CDIM / 4; i += 256) {
            float4 v = rp4[i];
            int base = i * 4;
            if (base + 0 != lab && (unsigned long long)monof(v.x) >= ucut) { lk1++; lS += v.x; lE += expf(v.x - M); }
            if (base + 1 != lab && (unsigned long long)monof(v.y) >= ucut) { lk1++; lS += v.y; lE += expf(v.y - M); }
            if (base + 2 != lab && (unsigned long long)monof(v.z) >= ucut) { lk1++; lS += v.z; lE += expf(v.z - M); }
            if (base + 3 != lab && (unsigned long long)monof(v.w) >= ucut) { lk1++; lS += v.w; lE += expf(v.w - M); }
        }
        int k1 = blockSumI(lk1, s_ired, tid);
        float S1 = blockSumF(lS, s_fred, tid);
        float E1 = blockSumF(lE, s_fred, tid);
        float vstar = unmonof((unsigned)lo);
        float n2 = (float)(NNEG - k1);
        Sneg = S1 + n2 * vstar;
        Sexp = E1 + n2 * expf(vstar - M);
    }

    if (tid == 0) {
        float lse = M + logf(Sexp + expf(posv - M));
        // targets: t0 = 0.9 + 0.1/500 = 0.9002, tj = 0.0002 (x50), sum = 0.9102
        g_rowloss[row] = 0.9102f * lse - 0.9002f * posv - 0.0002f * Sneg;
    }
}

// ===========================================================================
// Kernel 3: mean over rows -> scalar
// ===========================================================================
__global__ void k_final(float* __restrict__ out) {
    __shared__ float s[256];
    int tid = threadIdx.x;
    float a = 0.f;
    for (int i = tid; i < B_ROWS; i += 256) a += g_rowloss[i];
    s[tid] = a;
    __syncthreads();
    for (int st = 128; st > 0; st >>= 1) {
        if (tid < st) s[tid] += s[tid + st];
        __syncthreads();
    }
    if (tid == 0) out[0] = s[0] * (1.0f / (float)B_ROWS);
}

// ===========================================================================
extern "C" void kernel_launch(void* const* d_in, const int* in_sizes, int n_in,
                              void* d_out, int out_size) {
    const float* f = nullptr;
    const float* cen = nullptr;
    const void* lab = nullptr;
    for (int i = 0; i < n_in; i++) {
        long long sz = in_sizes[i];
        if (sz == (long long)B_ROWS * DK) f = (const float*)d_in[i];
        else if (sz == (long long)CDIM * DK) cen = (const float*)d_in[i];
        else if (sz == (long long)B_ROWS) lab = d_in[i];
    }
    if (!f) f = (const float*)d_in[0];
    if (!cen) cen = (const float*)d_in[1];
    if (!lab) lab = d_in[2];

    const int SMEM_SZ = 3 * 32768;  // three stages of (Ahi|Alo|Bhi|Blo)
    static int s_attr_done = 0;
    if (!s_attr_done) {
        cudaFuncSetAttribute(k_gemm_mma,
                             cudaFuncAttributeMaxDynamicSharedMemorySize, SMEM_SZ);
        s_attr_done = 1;
    }

    __nv_bfloat16 *ahi, *alo, *bhi, *blo;
    cudaGetSymbolAddress((void**)&ahi, g_ahi);
    cudaGetSymbolAddress((void**)&alo, g_alo);
    cudaGetSymbolAddress((void**)&bhi, g_bhi);
    cudaGetSymbolAddress((void**)&blo, g_blo);

    k_declab<<<1, 256>>>(lab);
    k_conv<<<(B_ROWS * DK) / (256 * 4), 256>>>(f, ahi, alo);
    k_conv<<<(CDIM * DK) / (256 * 4), 256>>>(cen, bhi, blo);
    dim3 grid(16, 512);  // x = M tiles (co-resident CTAs share a B tile), y = N
    k_gemm_mma<<<grid, 256, SMEM_SZ>>>();
    k_topk<<<B_ROWS, 256>>>();
    k_final<<<1, 256>>>((float*)d_out);
}

// round 11
// speedup vs baseline: 2.4236x; 1.3014x over previous
#include <cuda_runtime.h>
#include <cuda_bf16.h>
#include <cuda_fp16.h>
#include <cstdint>

#define B_ROWS 2048
#define CDIM   65536
#define DK     256
#define NNEG   50
#define CAP    6144
#define NTILES 512                 // 128-wide N tiles

// ---------------- device global scratch (no allocation calls) --------------
__device__ float g_scores[(size_t)B_ROWS * CDIM];          // 512 MB
__device__ float g_tilemax[(size_t)B_ROWS * NTILES];       // 4 MB (lab-excluded)
__device__ float g_rowloss[B_ROWS];
__device__ int   g_lab[B_ROWS];
__device__ __half g_ah[(size_t)B_ROWS * DK];               // A: single fp16
__device__ __half g_bh[(size_t)CDIM * DK];                 // B hi fp16 (32 MB)
__device__ __half g_bl[(size_t)CDIM * DK];                 // B lo fp16 (32 MB)

// ---------------- PTX helpers (baseline ISA only) --------------------------
__device__ __forceinline__ uint32_t smem_u32(const void* p) {
    uint32_t a;
    asm("{ .reg .u64 t; cvta.to.shared.u64 t, %1; cvt.u32.u64 %0, t; }"
        : "=r"(a) : "l"(p));
    return a;
}
__device__ __forceinline__ void cpa16(uint32_t dst, const void* src) {
    asm volatile("cp.async.cg.shared.global [%0], [%1], 16;"
                 :: "r"(dst), "l"(__cvta_generic_to_global(src)));
}
#define CPA_COMMIT() asm volatile("cp.async.commit_group;" ::: "memory")
#define CPA_WAIT0()  asm volatile("cp.async.wait_group 0;" ::: "memory")
#define CPA_WAIT1()  asm volatile("cp.async.wait_group 1;" ::: "memory")
#define CPA_WAIT2()  asm volatile("cp.async.wait_group 2;" ::: "memory")

#define LDSM4(r, addr)                                                         \
    asm volatile("ldmatrix.sync.aligned.m8n8.x4.shared.b16 {%0,%1,%2,%3},[%4];"\
        : "=r"((r)[0]), "=r"((r)[1]), "=r"((r)[2]), "=r"((r)[3]) : "r"(addr))

#define MMA16816(d, a, b0, b1)                                                 \
    asm volatile("mma.sync.aligned.m16n8k16.row.col.f32.f16.f16.f32 "          \
        "{%0,%1,%2,%3},{%4,%5,%6,%7},{%8,%9},{%0,%1,%2,%3};"                   \
        : "+f"((d)[0]), "+f"((d)[1]), "+f"((d)[2]), "+f"((d)[3])               \
        : "r"((a)[0]), "r"((a)[1]), "r"((a)[2]), "r"((a)[3]),                  \
          "r"(b0), "r"(b1))

__device__ __forceinline__ uint32_t pkh(__half a, __half b) {
    __half2 p; p.x = a; p.y = b;
    return *(uint32_t*)&p;
}

// ---------------- misc helpers ---------------------------------------------
__device__ __forceinline__ unsigned monof(float v) {
    unsigned b = __float_as_uint(v);
    return (b & 0x80000000u) ? ~b : (b | 0x80000000u);
}
__device__ __forceinline__ float unmonof(unsigned u) {
    unsigned b = (u & 0x80000000u) ? (u & 0x7fffffffu) : ~u;
    return __uint_as_float(b);
}
__device__ __forceinline__ int blockSumI(int v, int* sred, int tid) {
#pragma unroll
    for (int o = 16; o; o >>= 1) v += __shfl_xor_sync(0xffffffffu, v, o);
    if ((tid & 31) == 0) sred[tid >> 5] = v;
    __syncthreads();
    int tot = 0;
#pragma unroll
    for (int w = 0; w < 8; w++) tot += sred[w];
    __syncthreads();
    return tot;
}
__device__ __forceinline__ float blockSumF(float v, float* sred, int tid) {
#pragma unroll
    for (int o = 16; o; o >>= 1) v += __shfl_xor_sync(0xffffffffu, v, o);
    if ((tid & 31) == 0) sred[tid >> 5] = v;
    __syncthreads();
    float tot = 0.f;
#pragma unroll
    for (int w = 0; w < 8; w++) tot += sred[w];
    __syncthreads();
    return tot;
}
__device__ __forceinline__ float blockMinF(float v, float* sred, int tid) {
#pragma unroll
    for (int o = 16; o; o >>= 1) v = fminf(v, __shfl_xor_sync(0xffffffffu, v, o));
    if ((tid & 31) == 0) sred[tid >> 5] = v;
    __syncthreads();
    float tot = sred[0];
#pragma unroll
    for (int w = 1; w < 8; w++) tot = fminf(tot, sred[w]);
    __syncthreads();
    return tot;
}

// ===========================================================================
// Kernel 0: decode labels (int64 vs int32 ambiguity) + clamp
// ===========================================================================
__global__ void k_declab(const void* __restrict__ labp) {
    __shared__ int s_nz;
    const unsigned* w = (const unsigned*)labp;
    if (threadIdx.x == 0) s_nz = 0;
    __syncthreads();
    int nz = 0;
    for (int i = threadIdx.x; i < B_ROWS / 2; i += 256)
        if (w[2 * i + 1] != 0u) nz = 1;
    if (nz) atomicOr(&s_nz, 1);
    __syncthreads();
    bool is64 = (s_nz == 0);
    for (int r = threadIdx.x; r < B_ROWS; r += 256) {
        long long v = is64 ? ((const long long*)labp)[r] : (long long)((const int*)labp)[r];
        if (v < 0) v = 0;
        if (v > CDIM - 1) v = CDIM - 1;
        g_lab[r] = (int)v;
    }
}

// ===========================================================================
// Kernel 0b: conversions. A -> single fp16; B -> 2-term fp16 split.
// ===========================================================================
__global__ __launch_bounds__(256) void k_conv_a(const float* __restrict__ S,
                                                __half* __restrict__ H) {
    size_t i = (size_t)blockIdx.x * 256 + threadIdx.x;  // one float4 each
    float4 v = ((const float4*)S)[i];
    ((uint2*)H)[i] = make_uint2(
        pkh(__float2half(v.x), __float2half(v.y)),
        pkh(__float2half(v.z), __float2half(v.w)));
}
__global__ __launch_bounds__(256) void k_conv_b(const float* __restrict__ S,
                                                __half* __restrict__ H,
                                                __half* __restrict__ L) {
    size_t i = (size_t)blockIdx.x * 256 + threadIdx.x;  // one float4 each
    float4 v = ((const float4*)S)[i];
    __half h0 = __float2half(v.x), h1 = __float2half(v.y);
    __half h2 = __float2half(v.z), h3 = __float2half(v.w);
    __half l0 = __float2half(v.x - __half2float(h0));
    __half l1 = __float2half(v.y - __half2float(h1));
    __half l2 = __float2half(v.z - __half2float(h2));
    __half l3 = __float2half(v.w - __half2float(h3));
    ((uint2*)H)[i] = make_uint2(pkh(h0, h1), pkh(h2, h3));
    ((uint2*)L)[i] = make_uint2(pkh(l0, l1), pkh(l2, l3));
}

// ===========================================================================
// Kernel 1: HMMA GEMM. CTA tile 128(M)x128(N), 8 warps 2x4 (warp 64x32).
// fp16 2-pass: A(fp16) * Bh + A(fp16) * Bl, fp32 accumulate.
// 4-stage cp.async pipeline, ONE __syncthreads per stage.
// Stage = k-chunk of 32, XOR-swizzled 64B rows (piece ^= (row>>1)&3):
//   A 0, Bh 8192, Bl 16384   (24576/stage, x4 = 96KB, 2 CTA/SM)
// Epilogue: streaming score store + lab-excluded per-row tile max.
// ===========================================================================
__global__ __launch_bounds__(256, 2) void k_gemm_mma() {
    extern __shared__ __align__(16) char smem[];
    const uint32_t sb = smem_u32(smem);
    const int tid = threadIdx.x, lane = tid & 31, wid = tid >> 5;
    const int wm = wid & 1, wn = wid >> 1;          // warp grid 2(M) x 4(N)
    const int g = lane >> 2, tig = lane & 3;
    const int m0 = blockIdx.x * 128;
    const int n0t = blockIdx.y;                      // 128-wide N tile index

    float acc[4][4][4] = {};                         // [mi][ni][4]

    // loader lane mapping: row 0..63 (+64), 16B piece 0..3
    const int lrow = tid >> 2, lpc = tid & 3;
    const uint32_t swzL = (uint32_t)((lpc ^ ((lrow >> 1) & 3)) * 16);

    // ldmatrix lane constants (xor term is lane-constant within each frag)
    const int r15 = lane & 15, khalf = (lane >> 4) & 1;
    const uint32_t aBase = (uint32_t)((wm * 64 + r15) * 64);
    const uint32_t aS0 = (uint32_t)(((khalf) ^ ((r15 >> 1) & 3)) * 16);
    const int rb = (lane & 7) + ((lane >> 4) & 1) * 8, kbh = (lane >> 3) & 1;
    const uint32_t bBase = (uint32_t)((wn * 32 + rb) * 64);
    const uint32_t bS0 = (uint32_t)(((kbh) ^ ((rb >> 1) & 3)) * 16);

#define LOAD_STAGE(kt, bufi)                                                   \
    do {                                                                       \
        uint32_t st_ = sb + (bufi) * 24576;                                    \
        int kof_ = (kt) * 32 + lpc * 8;                                        \
        _Pragma("unroll")                                                      \
        for (int h_ = 0; h_ < 2; h_++) {                                       \
            int r_ = lrow + h_ * 64;                                           \
            size_t ga_ = (size_t)(m0 + r_) * DK + kof_;                        \
            size_t gb_ = (size_t)(n0t * 128 + r_) * DK + kof_;                 \
            uint32_t so_ = st_ + r_ * 64 + swzL;                               \
            cpa16(so_ +     0, g_ah + ga_);                                    \
            cpa16(so_ +  8192, g_bh + gb_);                                    \
            cpa16(so_ + 16384, g_bl + gb_);                                    \
        }                                                                      \
        CPA_COMMIT();                                                          \
    } while (0)

    LOAD_STAGE(0, 0);
    LOAD_STAGE(1, 1);
    LOAD_STAGE(2, 2);

#pragma unroll 1
    for (int kt = 0; kt < 8; kt++) {
        if (kt < 6) CPA_WAIT2();
        else if (kt == 6) CPA_WAIT1();
        else CPA_WAIT0();
        __syncthreads();
        if (kt + 3 < 8) LOAD_STAGE(kt + 3, (kt + 3) & 3);

        const uint32_t st = sb + (kt & 3) * 24576;
#pragma unroll
        for (int kk = 0; kk < 2; kk++) {
            const uint32_t aS = kk ? (aS0 ^ 32) : aS0;
            const uint32_t bS = kk ? (bS0 ^ 32) : bS0;
            uint32_t a[4][4], bh[4][2], bl[4][2];
#pragma unroll
            for (int mi = 0; mi < 4; mi++)
                LDSM4(a[mi], st + aBase + mi * 1024 + aS);
#pragma unroll
            for (int p = 0; p < 2; p++) {
                uint32_t r4[4];
                LDSM4(r4, st + 8192 + bBase + p * 1024 + bS);
                bh[2 * p][0] = r4[0]; bh[2 * p][1] = r4[1];
                bh[2 * p + 1][0] = r4[2]; bh[2 * p + 1][1] = r4[3];
                LDSM4(r4, st + 16384 + bBase + p * 1024 + bS);
                bl[2 * p][0] = r4[0]; bl[2 * p][1] = r4[1];
                bl[2 * p + 1][0] = r4[2]; bl[2 * p + 1][1] = r4[3];
            }
#pragma unroll
            for (int mi = 0; mi < 4; mi++)
#pragma unroll
                for (int ni = 0; ni < 4; ni++)
                    MMA16816(acc[mi][ni], a[mi], bh[ni][0], bh[ni][1]);
#pragma unroll
            for (int mi = 0; mi < 4; mi++)
#pragma unroll
                for (int ni = 0; ni < 4; ni++)
                    MMA16816(acc[mi][ni], a[mi], bl[ni][0], bl[ni][1]);
        }
    }
#undef LOAD_STAGE
    __syncthreads();   // smem reuse for the reduction below

    // ---- epilogue: store scores + lab-excluded row max for this tile ----
    float* sf = (float*)smem;  // [4 wn][128 rows]
#pragma unroll
    for (int mi = 0; mi < 4; mi++) {
        int row0 = m0 + wm * 64 + mi * 16 + g;
        int row1 = row0 + 8;
        int lab0 = g_lab[row0], lab1 = g_lab[row1];
        float mx0 = -3.402823466e38f, mx1 = -3.402823466e38f;
#pragma unroll
        for (int ni = 0; ni < 4; ni++) {
            int col = n0t * 128 + wn * 32 + ni * 8 + tig * 2;
            float c0 = acc[mi][ni][0], c1 = acc[mi][ni][1];
            float c2 = acc[mi][ni][2], c3 = acc[mi][ni][3];
            __stcs((float2*)(g_scores + (size_t)row0 * CDIM + col),
                   make_float2(c0, c1));
            __stcs((float2*)(g_scores + (size_t)row1 * CDIM + col),
                   make_float2(c2, c3));
            if (col != lab0)     mx0 = fmaxf(mx0, c0);
            if (col + 1 != lab0) mx0 = fmaxf(mx0, c1);
            if (col != lab1)     mx1 = fmaxf(mx1, c2);
            if (col + 1 != lab1) mx1 = fmaxf(mx1, c3);
        }
#pragma unroll
        for (int o = 1; o <= 2; o <<= 1) {
            mx0 = fmaxf(mx0, __shfl_xor_sync(0xffffffffu, mx0, o));
            mx1 = fmaxf(mx1, __shfl_xor_sync(0xffffffffu, mx1, o));
        }
        if (tig == 0) {
            sf[wn * 128 + wm * 64 + mi * 16 + g]     = mx0;
            sf[wn * 128 + wm * 64 + mi * 16 + g + 8] = mx1;
        }
    }
    __syncthreads();
    if (tid < 128) {
        float m = fmaxf(fmaxf(sf[tid], sf[128 + tid]),
                        fmaxf(sf[256 + tid], sf[384 + tid]));
        g_tilemax[(size_t)(m0 + tid) * NTILES + n0t] = m;
    }
}

// ===========================================================================
// Kernel 2: per row -> exact top-50 negatives. Pass A: 512 lab-excluded
// tile maxima (2KB/row) -> theta. Pass B: scan ONLY tiles with
// tilemax >= theta (exact filter; ~50 tiles/row), compact candidates,
// binary search on monotone keys. One 256-thread block per row.
// ===========================================================================
__global__ __launch_bounds__(256) void k_topk() {
    const int row = blockIdx.x;
    const int tid = threadIdx.x;
    const float* rp = g_scores + (size_t)row * CDIM;
    const int lab = g_lab[row];

    __shared__ float    s_max[256];
    __shared__ unsigned s_list[CAP];
    __shared__ unsigned short s_tiles[NTILES];
    __shared__ unsigned s_cnt, s_nt;
    __shared__ int      s_ired[8];
    __shared__ float    s_fred[8];

    // ---- pass A: thread max over 2 tile-maxima ----
    const float2* tm2 = (const float2*)(g_tilemax + (size_t)row * NTILES);
    float2 tv = tm2[tid];
    float lmax = fmaxf(tv.x, tv.y);
    s_max[tid] = lmax;
    __syncthreads();

    float gmax = -3.402823466e38f;
    int c = 0;
#pragma unroll 8
    for (int j = 0; j < 256; j++) {
        float m = s_max[j];
        gmax = fmaxf(gmax, m);
        c += (m > lmax);
    }
    float cand = (c < NNEG) ? lmax : 3.402823466e38f;
    float theta = blockMinF(cand, s_fred, tid);   // <= v50, count(>=theta) >= 50

    float posv = rp[lab];
    float M = fmaxf(gmax, posv);
    if (tid == 0) { s_cnt = 0; s_nt = 0; }
    __syncthreads();

    // ---- pass B: list hot tiles, then warp-per-tile candidate compaction ----
    if (tv.x >= theta) { unsigned p = atomicAdd(&s_nt, 1u); s_tiles[p] = (unsigned short)(2 * tid); }
    if (tv.y >= theta) { unsigned p = atomicAdd(&s_nt, 1u); s_tiles[p] = (unsigned short)(2 * tid + 1); }
    __syncthreads();
    const int nt = (int)s_nt;
    const int lane = tid & 31, w = tid >> 5;
    for (int cb = 0; cb < nt; cb += 8) {
        int li = cb + w;
        if (li < nt) {
            int t = s_tiles[li];
            int base = t * 128 + lane * 4;
            float4 v = *(const float4*)(rp + base);
            if (v.x >= theta && base + 0 != lab) { unsigned p = atomicAdd(&s_cnt, 1u); if (p < CAP) s_list[p] = monof(v.x); }
            if (v.y >= theta && base + 1 != lab) { unsigned p = atomicAdd(&s_cnt, 1u); if (p < CAP) s_list[p] = monof(v.y); }
            if (v.z >= theta && base + 2 != lab) { unsigned p = atomicAdd(&s_cnt, 1u); if (p < CAP) s_list[p] = monof(v.z); }
            if (v.w >= theta && base + 3 != lab) { unsigned p = atomicAdd(&s_cnt, 1u); if (p < CAP) s_list[p] = monof(v.w); }
        }
    }
    __syncthreads();
    unsigned cnt = s_cnt;

    float Sneg, Sexp;

    if (cnt <= CAP) {
        unsigned long long lo = (unsigned long long)monof(theta);
        unsigned long long hi = 0xffffffffull;
        while (lo < hi) {
            unsigned long long mid = lo + (hi - lo + 1) / 2;
            int lc = 0;
            for (unsigned i = tid; i < cnt; i += 256)
                lc += ((unsigned long long)s_list[i] >= mid);
            int tot = blockSumI(lc, s_ired, tid);
            if (tot >= NNEG) lo = mid; else hi = mid - 1;
        }
        unsigned long long ucut = lo + 1;
        int lk1 = 0; float lS = 0.f, lE = 0.f;
        for (unsigned i = tid; i < cnt; i += 256) {
            unsigned long long u = s_list[i];
            if (u >= ucut) {
                float x = unmonof((unsigned)u);
                lk1++; lS += x; lE += expf(x - M);
            }
        }
        int k1 = blockSumI(lk1, s_ired, tid);
        float S1 = blockSumF(lS, s_fred, tid);
        float E1 = blockSumF(lE, s_fred, tid);
        float vstar = unmonof((unsigned)lo);
        float n2 = (float)(NNEG - k1);
        Sneg = S1 + n2 * vstar;
        Sexp = E1 + n2 * expf(vstar - M);
    } else {
        // exact fallback (massive ties): binary search with full-row scans
        const float4* rp4 = (const float4*)rp;
        unsigned long long lo = (unsigned long long)monof(theta);
        unsigned long long hi = 0xffffffffull;
        while (lo < hi) {
            unsigned long long mid = lo + (hi - lo + 1) / 2;
            int lc = 0;
            for (int i = tid; i < CDIM / 4; i += 256) {
                float4 v = rp4[i];
                int base = i * 4;
                if (base + 0 != lab) lc += ((unsigned long long)monof(v.x) >= mid);
                if (base + 1 != lab) lc += ((unsigned long long)monof(v.y) >= mid);
                if (base + 2 != lab) lc += ((unsigned long long)monof(v.z) >= mid);
                if (base + 3 != lab) lc += ((unsigned long long)monof(v.w) >= mid);
            }
            int tot = blockSumI(lc, s_ired, tid);
            if (tot >= NNEG) lo = mid; else hi = mid - 1;
        }
        unsigned long long ucut = lo + 1;
        int lk1 = 0; float lS = 0.f, lE = 0.f;
        for (int i = tid; i < CDIM / 4; i += 256) {
            float4 v = rp4[i];
            int base = i * 4;
            if (base + 0 != lab && (unsigned long long)monof(v.x) >= ucut) { lk1++; lS += v.x; lE += expf(v.x - M); }
            if (base + 1 != lab && (unsigned long long)monof(v.y) >= ucut) { lk1++; lS += v.y; lE += expf(v.y - M); }
            if (base + 2 != lab && (unsigned long long)monof(v.z) >= ucut) { lk1++; lS += v.z; lE += expf(v.z - M); }
            if (base + 3 != lab && (unsigned long long)monof(v.w) >= ucut) { lk1++; lS += v.w; lE += expf(v.w - M); }
        }
        int k1 = blockSumI(lk1, s_ired, tid);
        float S1 = blockSumF(lS, s_fred, tid);
        float E1 = blockSumF(lE, s_fred, tid);
        float vstar = unmonof((unsigned)lo);
        float n2 = (float)(NNEG - k1);
        Sneg = S1 + n2 * vstar;
        Sexp = E1 + n2 * expf(vstar - M);
    }

    if (tid == 0) {
        float lse = M + logf(Sexp + expf(posv - M));
        // targets: t0 = 0.9 + 0.1/500 = 0.9002, tj = 0.0002 (x50), sum = 0.9102
        g_rowloss[row] = 0.9102f * lse - 0.9002f * posv - 0.0002f * Sneg;
    }
}

// ===========================================================================
// Kernel 3: mean over rows -> scalar
// ===========================================================================
__global__ void k_final(float* __restrict__ out) {
    __shared__ float s[256];
    int tid = threadIdx.x;
    float a = 0.f;
    for (int i = tid; i < B_ROWS; i += 256) a += g_rowloss[i];
    s[tid] = a;
    __syncthreads();
    for (int st = 128; st > 0; st >>= 1) {
        if (tid < st) s[tid] += s[tid + st];
        __syncthreads();
    }
    if (tid == 0) out[0] = s[0] * (1.0f / (float)B_ROWS);
}

// ===========================================================================
extern "C" void kernel_launch(void* const* d_in, const int* in_sizes, int n_in,
                              void* d_out, int out_size) {
    const float* f = nullptr;
    const float* cen = nullptr;
    const void* lab = nullptr;
    for (int i = 0; i < n_in; i++) {
        long long sz = in_sizes[i];
        if (sz == (long long)B_ROWS * DK) f = (const float*)d_in[i];
        else if (sz == (long long)CDIM * DK) cen = (const float*)d_in[i];
        else if (sz == (long long)B_ROWS) lab = d_in[i];
    }
    if (!f) f = (const float*)d_in[0];
    if (!cen) cen = (const float*)d_in[1];
    if (!lab) lab = d_in[2];

    const int SMEM_SZ = 4 * 24576;  // four stages of (A|Bh|Bl)
    static int s_attr_done = 0;
    if (!s_attr_done) {
        cudaFuncSetAttribute(k_gemm_mma,
                             cudaFuncAttributeMaxDynamicSharedMemorySize, SMEM_SZ);
        s_attr_done = 1;
    }

    __half *ah, *bh, *bl;
    cudaGetSymbolAddress((void**)&ah, g_ah);
    cudaGetSymbolAddress((void**)&bh, g_bh);
    cudaGetSymbolAddress((void**)&bl, g_bl);

    k_declab<<<1, 256>>>(lab);
    k_conv_a<<<(B_ROWS * DK) / (256 * 4), 256>>>(f, ah);
    k_conv_b<<<(CDIM * DK) / (256 * 4), 256>>>(cen, bh, bl);
    dim3 grid(16, 512);  // x = M tiles (co-resident CTAs share a B tile), y = N
    k_gemm_mma<<<grid, 256, SMEM_SZ>>>();
    k_topk<<<B_ROWS, 256>>>();
    k_final<<<1, 256>>>((float*)d_out);
}

// round 12
// speedup vs baseline: 3.2490x; 1.3406x over previous
#include <cuda_runtime.h>
#include <cuda_bf16.h>
#include <cuda_fp16.h>
#include <cstdint>

#define B_ROWS 2048
#define CDIM   65536
#define DK     256
#define NNEG   50
#define CAP    6144
#define NTILES 512                 // 128-wide N tiles

// ---------------- device global scratch (no allocation calls) --------------
__device__ float g_scores[(size_t)B_ROWS * CDIM];          // 512 MB
__device__ float g_tilemax[(size_t)B_ROWS * NTILES];       // 4 MB (lab-excluded)
__device__ float g_rowloss[B_ROWS];
__device__ int   g_lab[B_ROWS];
__device__ __half g_ah[(size_t)B_ROWS * DK];               // A fp16
__device__ __half g_bh[(size_t)CDIM * DK];                 // B fp16 (32 MB)

// ---------------- PTX helpers (baseline ISA only) --------------------------
__device__ __forceinline__ uint32_t smem_u32(const void* p) {
    uint32_t a;
    asm("{ .reg .u64 t; cvta.to.shared.u64 t, %1; cvt.u32.u64 %0, t; }"
        : "=r"(a) : "l"(p));
    return a;
}
__device__ __forceinline__ void cpa16(uint32_t dst, const void* src) {
    asm volatile("cp.async.cg.shared.global [%0], [%1], 16;"
                 :: "r"(dst), "l"(__cvta_generic_to_global(src)));
}
#define CPA_COMMIT() asm volatile("cp.async.commit_group;" ::: "memory")
#define CPA_WAIT0()  asm volatile("cp.async.wait_group 0;" ::: "memory")
#define CPA_WAIT1()  asm volatile("cp.async.wait_group 1;" ::: "memory")
#define CPA_WAIT2()  asm volatile("cp.async.wait_group 2;" ::: "memory")
#define CPA_WAIT3()  asm volatile("cp.async.wait_group 3;" ::: "memory")
#define CPA_WAIT4()  asm volatile("cp.async.wait_group 4;" ::: "memory")

#define LDSM4(r, addr)                                                         \
    asm volatile("ldmatrix.sync.aligned.m8n8.x4.shared.b16 {%0,%1,%2,%3},[%4];"\
        : "=r"((r)[0]), "=r"((r)[1]), "=r"((r)[2]), "=r"((r)[3]) : "r"(addr))

#define MMA16816(d, a, b0, b1)                                                 \
    asm volatile("mma.sync.aligned.m16n8k16.row.col.f32.f16.f16.f32 "          \
        "{%0,%1,%2,%3},{%4,%5,%6,%7},{%8,%9},{%0,%1,%2,%3};"                   \
        : "+f"((d)[0]), "+f"((d)[1]), "+f"((d)[2]), "+f"((d)[3])               \
        : "r"((a)[0]), "r"((a)[1]), "r"((a)[2]), "r"((a)[3]),                  \
          "r"(b0), "r"(b1))

__device__ __forceinline__ uint32_t pkh(__half a, __half b) {
    __half2 p; p.x = a; p.y = b;
    return *(uint32_t*)&p;
}

// ---------------- misc helpers ---------------------------------------------
__device__ __forceinline__ unsigned monof(float v) {
    unsigned b = __float_as_uint(v);
    return (b & 0x80000000u) ? ~b : (b | 0x80000000u);
}
__device__ __forceinline__ float unmonof(unsigned u) {
    unsigned b = (u & 0x80000000u) ? (u & 0x7fffffffu) : ~u;
    return __uint_as_float(b);
}
__device__ __forceinline__ int blockSumI(int v, int* sred, int tid) {
#pragma unroll
    for (int o = 16; o; o >>= 1) v += __shfl_xor_sync(0xffffffffu, v, o);
    if ((tid & 31) == 0) sred[tid >> 5] = v;
    __syncthreads();
    int tot = 0;
#pragma unroll
    for (int w = 0; w < 8; w++) tot += sred[w];
    __syncthreads();
    return tot;
}
__device__ __forceinline__ float blockSumF(float v, float* sred, int tid) {
#pragma unroll
    for (int o = 16; o; o >>= 1) v += __shfl_xor_sync(0xffffffffu, v, o);
    if ((tid & 31) == 0) sred[tid >> 5] = v;
    __syncthreads();
    float tot = 0.f;
#pragma unroll
    for (int w = 0; w < 8; w++) tot += sred[w];
    __syncthreads();
    return tot;
}
__device__ __forceinline__ float blockMinF(float v, float* sred, int tid) {
#pragma unroll
    for (int o = 16; o; o >>= 1) v = fminf(v, __shfl_xor_sync(0xffffffffu, v, o));
    if ((tid & 31) == 0) sred[tid >> 5] = v;
    __syncthreads();
    float tot = sred[0];
#pragma unroll
    for (int w = 1; w < 8; w++) tot = fminf(tot, sred[w]);
    __syncthreads();
    return tot;
}

// ===========================================================================
// Kernel 0: decode labels (int64 vs int32 ambiguity) + clamp
// ===========================================================================
__global__ void k_declab(const void* __restrict__ labp) {
    __shared__ int s_nz;
    const unsigned* w = (const unsigned*)labp;
    if (threadIdx.x == 0) s_nz = 0;
    __syncthreads();
    int nz = 0;
    for (int i = threadIdx.x; i < B_ROWS / 2; i += 256)
        if (w[2 * i + 1] != 0u) nz = 1;
    if (nz) atomicOr(&s_nz, 1);
    __syncthreads();
    bool is64 = (s_nz == 0);
    for (int r = threadIdx.x; r < B_ROWS; r += 256) {
        long long v = is64 ? ((const long long*)labp)[r] : (long long)((const int*)labp)[r];
        if (v < 0) v = 0;
        if (v > CDIM - 1) v = CDIM - 1;
        g_lab[r] = (int)v;
    }
}

// ===========================================================================
// Kernel 0b: fp32 -> fp16 conversion (round-to-nearest)
// ===========================================================================
__global__ __launch_bounds__(256) void k_conv(const float* __restrict__ S,
                                              __half* __restrict__ H) {
    size_t i = (size_t)blockIdx.x * 256 + threadIdx.x;  // one float4 each
    float4 v = ((const float4*)S)[i];
    ((uint2*)H)[i] = make_uint2(
        pkh(__float2half(v.x), __float2half(v.y)),
        pkh(__float2half(v.z), __float2half(v.w)));
}

// ===========================================================================
// Kernel 1: HMMA GEMM. CTA tile 128(M)x128(N), 8 warps 2x4 (warp 64x32).
// Pure fp16 single pass: A * B, fp32 accumulate.
// 6-stage cp.async pipeline (prefetch distance 5), ONE __syncthreads/stage.
// Stage = k-chunk of 32, XOR-swizzled 64B rows (piece ^= (row>>1)&3):
//   A 0, B 8192   (16384/stage, x6 = 96KB, 2 CTA/SM)
// Epilogue: streaming score store + lab-excluded per-row tile max.
// ===========================================================================
__global__ __launch_bounds__(256, 2) void k_gemm_mma() {
    extern __shared__ __align__(16) char smem[];
    const uint32_t sb = smem_u32(smem);
    const int tid = threadIdx.x, lane = tid & 31, wid = tid >> 5;
    const int wm = wid & 1, wn = wid >> 1;          // warp grid 2(M) x 4(N)
    const int g = lane >> 2, tig = lane & 3;
    const int m0 = blockIdx.x * 128;
    const int n0t = blockIdx.y;                      // 128-wide N tile index

    float acc[4][4][4] = {};                         // [mi][ni][4]

    // loader lane mapping: row 0..63 (+64), 16B piece 0..3
    const int lrow = tid >> 2, lpc = tid & 3;
    const uint32_t swzL = (uint32_t)((lpc ^ ((lrow >> 1) & 3)) * 16);

    // ldmatrix lane constants (xor term is lane-constant within each frag)
    const int r15 = lane & 15, khalf = (lane >> 4) & 1;
    const uint32_t aBase = (uint32_t)((wm * 64 + r15) * 64);
    const uint32_t aS0 = (uint32_t)(((khalf) ^ ((r15 >> 1) & 3)) * 16);
    const int rb = (lane & 7) + ((lane >> 4) & 1) * 8, kbh = (lane >> 3) & 1;
    const uint32_t bBase = (uint32_t)((wn * 32 + rb) * 64);
    const uint32_t bS0 = (uint32_t)(((kbh) ^ ((rb >> 1) & 3)) * 16);

#define LOAD_STAGE(kt, bufi)                                                   \
    do {                                                                       \
        uint32_t st_ = sb + (bufi) * 16384;                                    \
        int kof_ = (kt) * 32 + lpc * 8;                                        \
        _Pragma("unroll")                                                      \
        for (int h_ = 0; h_ < 2; h_++) {                                       \
            int r_ = lrow + h_ * 64;                                           \
            size_t ga_ = (size_t)(m0 + r_) * DK + kof_;                        \
            size_t gb_ = (size_t)(n0t * 128 + r_) * DK + kof_;                 \
            uint32_t so_ = st_ + r_ * 64 + swzL;                               \
            cpa16(so_ +    0, g_ah + ga_);                                     \
            cpa16(so_ + 8192, g_bh + gb_);                                     \
        }                                                                      \
        CPA_COMMIT();                                                          \
    } while (0)

    LOAD_STAGE(0, 0);
    LOAD_STAGE(1, 1);
    LOAD_STAGE(2, 2);
    LOAD_STAGE(3, 3);
    LOAD_STAGE(4, 4);

#pragma unroll 1
    for (int kt = 0; kt < 8; kt++) {
        // pending-group budget so stage kt is complete
        if (kt <= 3)      CPA_WAIT4();
        else if (kt == 4) CPA_WAIT3();
        else if (kt == 5) CPA_WAIT2();
        else if (kt == 6) CPA_WAIT1();
        else              CPA_WAIT0();
        __syncthreads();
        if (kt + 5 < 8) LOAD_STAGE(kt + 5, (kt + 5) % 6);

        const uint32_t st = sb + (kt % 6) * 16384;
#pragma unroll
        for (int kk = 0; kk < 2; kk++) {
            const uint32_t aS = kk ? (aS0 ^ 32) : aS0;
            const uint32_t bS = kk ? (bS0 ^ 32) : bS0;
            uint32_t a[4][4], bh[4][2];
#pragma unroll
            for (int mi = 0; mi < 4; mi++)
                LDSM4(a[mi], st + aBase + mi * 1024 + aS);
#pragma unroll
            for (int p = 0; p < 2; p++) {
                uint32_t r4[4];
                LDSM4(r4, st + 8192 + bBase + p * 1024 + bS);
                bh[2 * p][0] = r4[0]; bh[2 * p][1] = r4[1];
                bh[2 * p + 1][0] = r4[2]; bh[2 * p + 1][1] = r4[3];
            }
#pragma unroll
            for (int mi = 0; mi < 4; mi++)
#pragma unroll
                for (int ni = 0; ni < 4; ni++)
                    MMA16816(acc[mi][ni], a[mi], bh[ni][0], bh[ni][1]);
        }
    }
#undef LOAD_STAGE
    __syncthreads();   // smem reuse for the reduction below

    // ---- epilogue: store scores + lab-excluded row max for this tile ----
    float* sf = (float*)smem;  // [4 wn][128 rows]
#pragma unroll
    for (int mi = 0; mi < 4; mi++) {
        int row0 = m0 + wm * 64 + mi * 16 + g;
        int row1 = row0 + 8;
        int lab0 = g_lab[row0], lab1 = g_lab[row1];
        float mx0 = -3.402823466e38f, mx1 = -3.402823466e38f;
#pragma unroll
        for (int ni = 0; ni < 4; ni++) {
            int col = n0t * 128 + wn * 32 + ni * 8 + tig * 2;
            float c0 = acc[mi][ni][0], c1 = acc[mi][ni][1];
            float c2 = acc[mi][ni][2], c3 = acc[mi][ni][3];
            __stcs((float2*)(g_scores + (size_t)row0 * CDIM + col),
                   make_float2(c0, c1));
            __stcs((float2*)(g_scores + (size_t)row1 * CDIM + col),
                   make_float2(c2, c3));
            if (col != lab0)     mx0 = fmaxf(mx0, c0);
            if (col + 1 != lab0) mx0 = fmaxf(mx0, c1);
            if (col != lab1)     mx1 = fmaxf(mx1, c2);
            if (col + 1 != lab1) mx1 = fmaxf(mx1, c3);
        }
#pragma unroll
        for (int o = 1; o <= 2; o <<= 1) {
            mx0 = fmaxf(mx0, __shfl_xor_sync(0xffffffffu, mx0, o));
            mx1 = fmaxf(mx1, __shfl_xor_sync(0xffffffffu, mx1, o));
        }
        if (tig == 0) {
            sf[wn * 128 + wm * 64 + mi * 16 + g]     = mx0;
            sf[wn * 128 + wm * 64 + mi * 16 + g + 8] = mx1;
        }
    }
    __syncthreads();
    if (tid < 128) {
        float m = fmaxf(fmaxf(sf[tid], sf[128 + tid]),
                        fmaxf(sf[256 + tid], sf[384 + tid]));
        g_tilemax[(size_t)(m0 + tid) * NTILES + n0t] = m;
    }
}

// ===========================================================================
// Kernel 2: per row -> exact top-50 negatives. Pass A: 512 lab-excluded
// tile maxima (2KB/row) -> theta. Pass B: scan ONLY tiles with
// tilemax >= theta (exact filter; ~50 tiles/row), compact candidates,
// binary search on monotone keys. One 256-thread block per row.
// ===========================================================================
__global__ __launch_bounds__(256) void k_topk() {
    const int row = blockIdx.x;
    const int tid = threadIdx.x;
    const float* rp = g_scores + (size_t)row * CDIM;
    const int lab = g_lab[row];

    __shared__ float    s_max[256];
    __shared__ unsigned s_list[CAP];
    __shared__ unsigned short s_tiles[NTILES];
    __shared__ unsigned s_cnt, s_nt;
    __shared__ int      s_ired[8];
    __shared__ float    s_fred[8];

    // ---- pass A: thread max over 2 tile-maxima ----
    const float2* tm2 = (const float2*)(g_tilemax + (size_t)row * NTILES);
    float2 tv = tm2[tid];
    float lmax = fmaxf(tv.x, tv.y);
    s_max[tid] = lmax;
    __syncthreads();

    float gmax = -3.402823466e38f;
    int c = 0;
#pragma unroll 8
    for (int j = 0; j < 256; j++) {
        float m = s_max[j];
        gmax = fmaxf(gmax, m);
        c += (m > lmax);
    }
    float cand = (c < NNEG) ? lmax : 3.402823466e38f;
    float theta = blockMinF(cand, s_fred, tid);   // <= v50, count(>=theta) >= 50

    float posv = rp[lab];
    float M = fmaxf(gmax, posv);
    if (tid == 0) { s_cnt = 0; s_nt = 0; }
    __syncthreads();

    // ---- pass B: list hot tiles, then warp-per-tile candidate compaction ----
    if (tv.x >= theta) { unsigned p = atomicAdd(&s_nt, 1u); s_tiles[p] = (unsigned short)(2 * tid); }
    if (tv.y >= theta) { unsigned p = atomicAdd(&s_nt, 1u); s_tiles[p] = (unsigned short)(2 * tid + 1); }
    __syncthreads();
    const int nt = (int)s_nt;
    const int lane = tid & 31, w = tid >> 5;
    for (int cb = 0; cb < nt; cb += 8) {
        int li = cb + w;
        if (li < nt) {
            int t = s_tiles[li];
            int base = t * 128 + lane * 4;
            float4 v = *(const float4*)(rp + base);
            if (v.x >= theta && base + 0 != lab) { unsigned p = atomicAdd(&s_cnt, 1u); if (p < CAP) s_list[p] = monof(v.x); }
            if (v.y >= theta && base + 1 != lab) { unsigned p = atomicAdd(&s_cnt, 1u); if (p < CAP) s_list[p] = monof(v.y); }
            if (v.z >= theta && base + 2 != lab) { unsigned p = atomicAdd(&s_cnt, 1u); if (p < CAP) s_list[p] = monof(v.z); }
            if (v.w >= theta && base + 3 != lab) { unsigned p = atomicAdd(&s_cnt, 1u); if (p < CAP) s_list[p] = monof(v.w); }
        }
    }
    __syncthreads();
    unsigned cnt = s_cnt;

    float Sneg, Sexp;

    if (cnt <= CAP) {
        unsigned long long lo = (unsigned long long)monof(theta);
        unsigned long long hi = 0xffffffffull;
        while (lo < hi) {
            unsigned long long mid = lo + (hi - lo + 1) / 2;
            int lc = 0;
            for (unsigned i = tid; i < cnt; i += 256)
                lc += ((unsigned long long)s_list[i] >= mid);
            int tot = blockSumI(lc, s_ired, tid);
            if (tot >= NNEG) lo = mid; else hi = mid - 1;
        }
        unsigned long long ucut = lo + 1;
        int lk1 = 0; float lS = 0.f, lE = 0.f;
        for (unsigned i = tid; i < cnt; i += 256) {
            unsigned long long u = s_list[i];
            if (u >= ucut) {
                float x = unmonof((unsigned)u);
                lk1++; lS += x; lE += expf(x - M);
            }
        }
        int k1 = blockSumI(lk1, s_ired, tid);
        float S1 = blockSumF(lS, s_fred, tid);
        float E1 = blockSumF(lE, s_fred, tid);
        float vstar = unmonof((unsigned)lo);
        float n2 = (float)(NNEG - k1);
        Sneg = S1 + n2 * vstar;
        Sexp = E1 + n2 * expf(vstar - M);
    } else {
        // exact fallback (massive ties): binary search with full-row scans
        const float4* rp4 = (const float4*)rp;
        unsigned long long lo = (unsigned long long)monof(theta);
        unsigned long long hi = 0xffffffffull;
        while (lo < hi) {
            unsigned long long mid = lo + (hi - lo + 1) / 2;
            int lc = 0;
            for (int i = tid; i < CDIM / 4; i += 256) {
                float4 v = rp4[i];
                int base = i * 4;
                if (base + 0 != lab) lc += ((unsigned long long)monof(v.x) >= mid);
                if (base + 1 != lab) lc += ((unsigned long long)monof(v.y) >= mid);
                if (base + 2 != lab) lc += ((unsigned long long)monof(v.z) >= mid);
                if (base + 3 != lab) lc += ((unsigned long long)monof(v.w) >= mid);
            }
            int tot = blockSumI(lc, s_ired, tid);
            if (tot >= NNEG) lo = mid; else hi = mid - 1;
        }
        unsigned long long ucut = lo + 1;
        int lk1 = 0; float lS = 0.f, lE = 0.f;
        for (int i = tid; i < CDIM / 4; i += 256) {
            float4 v = rp4[i];
            int base = i * 4;
            if (base + 0 != lab && (unsigned long long)monof(v.x) >= ucut) { lk1++; lS += v.x; lE += expf(v.x - M); }
            if (base + 1 != lab && (unsigned long long)monof(v.y) >= ucut) { lk1++; lS += v.y; lE += expf(v.y - M); }
            if (base + 2 != lab && (unsigned long long)monof(v.z) >= ucut) { lk1++; lS += v.z; lE += expf(v.z - M); }
            if (base + 3 != lab && (unsigned long long)monof(v.w) >= ucut) { lk1++; lS += v.w; lE += expf(v.w - M); }
        }
        int k1 = blockSumI(lk1, s_ired, tid);
        float S1 = blockSumF(lS, s_fred, tid);
        float E1 = blockSumF(lE, s_fred, tid);
        float vstar = unmonof((unsigned)lo);
        float n2 = (float)(NNEG - k1);
        Sneg = S1 + n2 * vstar;
        Sexp = E1 + n2 * expf(vstar - M);
    }

    if (tid == 0) {
        float lse = M + logf(Sexp + expf(posv - M));
        // targets: t0 = 0.9 + 0.1/500 = 0.9002, tj = 0.0002 (x50), sum = 0.9102
        g_rowloss[row] = 0.9102f * lse - 0.9002f * posv - 0.0002f * Sneg;
    }
}

// ===========================================================================
// Kernel 3: mean over rows -> scalar
// ===========================================================================
__global__ void k_final(float* __restrict__ out) {
    __shared__ float s[256];
    int tid = threadIdx.x;
    float a = 0.f;
    for (int i = tid; i < B_ROWS; i += 256) a += g_rowloss[i];
    s[tid] = a;
    __syncthreads();
    for (int st = 128; st > 0; st >>= 1) {
        if (tid < st) s[tid] += s[tid + st];
        __syncthreads();
    }
    if (tid == 0) out[0] = s[0] * (1.0f / (float)B_ROWS);
}

// ===========================================================================
extern "C" void kernel_launch(void* const* d_in, const int* in_sizes, int n_in,
                              void* d_out, int out_size) {
    const float* f = nullptr;
    const float* cen = nullptr;
    const void* lab = nullptr;
    for (int i = 0; i < n_in; i++) {
        long long sz = in_sizes[i];
        if (sz == (long long)B_ROWS * DK) f = (const float*)d_in[i];
        else if (sz == (long long)CDIM * DK) cen = (const float*)d_in[i];
        else if (sz == (long long)B_ROWS) lab = d_in[i];
    }
    if (!f) f = (const float*)d_in[0];
    if (!cen) cen = (const float*)d_in[1];
    if (!lab) lab = d_in[2];

    const int SMEM_SZ = 6 * 16384;  // six stages of (A|B)
    static int s_attr_done = 0;
    if (!s_attr_done) {
        cudaFuncSetAttribute(k_gemm_mma,
                             cudaFuncAttributeMaxDynamicSharedMemorySize, SMEM_SZ);
        s_attr_done = 1;
    }

    __half *ah, *bh;
    cudaGetSymbolAddress((void**)&ah, g_ah);
    cudaGetSymbolAddress((void**)&bh, g_bh);

    k_declab<<<1, 256>>>(lab);
    k_conv<<<(B_ROWS * DK) / (256 * 4), 256>>>(f, ah);
    k_conv<<<(CDIM * DK) / (256 * 4), 256>>>(cen, bh);
    dim3 grid(16, 512);  // x = M tiles (co-resident CTAs share a B tile), y = N
    k_gemm_mma<<<grid, 256, SMEM_SZ>>>();
    k_topk<<<B_ROWS, 256>>>();
    k_final<<<1, 256>>>((float*)d_out);
}